// round 14
// baseline (speedup 1.0000x reference)
#include <cuda_runtime.h>
#include <math.h>

#define BB 4096
#define TT 128
#define SS 12288              // 3 * BB channel-chains
#define NSLOT 126             // loss slots u = t-2, t in [2,127]
#define NG 125                // filtered-history slots, t in [2,126], m = t-2

// shared memory layout (floats)
#define SZ_Z   (384 * 33)             // z staged: [k=t*3+ch][lane] padded
#define SZ_SV  (3 * NSLOT * 32)       // Sv table: [ch][u][lane]
#define SZ_D   (NG * 96)              // Pc history: [m][tid]
#define SMEM_FLOATS (SZ_Z + SZ_SV + SZ_D)
#define SMEM_BYTES  (SMEM_FLOATS * 4)

// ---------------- device scratch (no allocations allowed) ----------------
__device__ float4 g_F[NG * SS];    // filtered p,v,Pa,Pb
__device__ float  g_bsum[128];     // per-block partials
__device__ unsigned int g_cnt;     // last-block gate (self-resetting)

static __device__ __forceinline__ float sigmoidf_(float x) {
    return 1.0f / (1.0f + expf(-x));
}
static __device__ __forceinline__ float tanh_fast(float x) {
    float y; asm("tanh.approx.f32 %0, %1;" : "=f"(y) : "f"(x)); return y;
}
static __device__ __forceinline__ float rcp_fast(float x) {
    float y; asm("rcp.approx.f32 %0, %1;" : "=f"(y) : "f"(x)); return y;
}

// ---------------- packed f32x2 helpers (FFMA2 path, sm_103a) ----------------
typedef unsigned long long u2;
static __device__ __forceinline__ u2 pk(float lo, float hi) {
    u2 r; asm("mov.b64 %0, {%1, %2};" : "=l"(r) : "f"(lo), "f"(hi)); return r;
}
static __device__ __forceinline__ void unpk(u2 a, float& lo, float& hi) {
    asm("mov.b64 {%0, %1}, %2;" : "=f"(lo), "=f"(hi) : "l"(a));
}
static __device__ __forceinline__ u2 fma2_(u2 a, u2 b, u2 c) {
    u2 d; asm("fma.rn.f32x2 %0, %1, %2, %3;" : "=l"(d) : "l"(a), "l"(b), "l"(c)); return d;
}
static __device__ __forceinline__ u2 mul2_(u2 a, u2 b) {
    u2 d; asm("mul.rn.f32x2 %0, %1, %2;" : "=l"(d) : "l"(a), "l"(b)); return d;
}
static __device__ __forceinline__ u2 add2_(u2 a, u2 b) {
    u2 d; asm("add.rn.f32x2 %0, %1, %2;" : "=l"(d) : "l"(a), "l"(b)); return d;
}
#define NEG2(a) ((a) ^ 0x8000000080000000ULL)

__global__ void __launch_bounds__(96, 1)
k_all(const float* __restrict__ params,
      const float* __restrict__ covp,
      const float* __restrict__ init_states,
      const float* __restrict__ zin,
      float* __restrict__ out)
{
    extern __shared__ float smem[];
    float* sZ  = smem;                   // [384][33]
    float* sSv = smem + SZ_Z;            // [3][126][32]
    float* sD  = smem + SZ_Z + SZ_SV;    // [125][96]
    __shared__ bool sLast;

    const int tid  = threadIdx.x;
    const int ch   = tid >> 5;           // warp index = channel
    const int lane = tid & 31;
    const int b    = (blockIdx.x << 5) + lane;
    const int s    = ch * BB + b;        // column in g_F

    // ---------- stage this block's measurements into smem (coalesced) ----------
    {
        const float* zblk = zin + (size_t)(blockIdx.x << 5) * (TT * 3);
#pragma unroll 4
        for (int lb = 0; lb < 32; lb++) {
            const float4 vz = reinterpret_cast<const float4*>(zblk + lb * 384)[tid];
            const int k = tid << 2;
            sZ[(k + 0) * 33 + lb] = vz.x;
            sZ[(k + 1) * 33 + lb] = vz.y;
            sZ[(k + 2) * 33 + lb] = vz.z;
            sZ[(k + 3) * 33 + lb] = vz.w;
        }
    }

    const float DT     = 1.0f / 120.0f;
    const float TWO_PI = 6.28318530717958647692f;
    const float INV2PI = 0.15915494309189533577f;
    const float FOLD   = 4.71238898038468985769f;

    const float friction = (tanhf(params[0]) + 1.0f) * 0.01f;
    const float damping  = (tanhf(params[1]) + 1.0f) * 0.01f;

    const bool  ang   = (ch == 2);
    const float r     = sigmoidf_(covp[ch]);
    const float qp    = sigmoidf_(covp[ang ? 5 : 3]);
    const float qv    = sigmoidf_(covp[ang ? 6 : 4]);
    const float gd    = 1.0f - DT * damping;
    const float Df_c    = ang ? 0.0f : DT * friction;
    const float Ag_c    = ang ? 0.0f : DT * friction * 100.0f;
    const float gdmAg_c = gd - Ag_c;
    const float wTP     = ang ? TWO_PI : 0.0f;
    const float FOLD_c  = ang ? FOLD : 3.0e38f;

    const u2 DT2 = pk(DT, DT);           // hoisted broadcast
    const u2 r2  = pk(r, r);

    float p, v, Pa = 0.01f, Pb = 0.0f, Pc = 0.01f;
    {
        const int pi = ang ? 4 : ch;
        const int vi = ang ? 5 : (ch + 2);
        p = init_states[b * 6 + pi];
        v = init_states[b * 6 + vi];
    }

    __syncthreads();   // z staged

#define ZLDS(t) sZ[((t) * 3 + ch) * 33 + lane]

    // =========================== FORWARD EKF (packed f32x2) ===========================
#define FW_MATH(zc)                                                              \
    do {                                                                         \
        const float th   = tanh_fast(100.0f * v);                                \
        const float spv_ = __fmaf_rn(-Df_c, th, gd * v);                         \
        const float g_   = __fmaf_rn(Ag_c, th * th, gdmAg_c);                    \
        /* {spp_, bdc} = fma2(DT, {v,Pc}, {p,Pb}) */                             \
        float spp_, bdc;                                                         \
        unpk(fma2_(DT2, pk(v, Pc), pk(p, Pb)), spp_, bdc);                       \
        const float ap   = __fmaf_rn(DT, Pb + bdc, Pa) + qp;                     \
        const float bp   = g_ * bdc;                                             \
        const float cpv  = __fmaf_rn(g_ * g_, Pc, qv);                           \
        float innov = (zc) - spp_;                                               \
        innov = __fmaf_rn(-wTP, rintf(innov * INV2PI), innov);                   \
        const float inv = rcp_fast(ap + r);                                      \
        /* {K0,K1} = {ap,bp} * inv */                                            \
        const u2 KK = mul2_(pk(ap, bp), pk(inv, inv));                           \
        /* {p',v'} = fma2(KK, innov, {spp_,spv_}) */                             \
        unpk(fma2_(KK, pk(innov, innov), pk(spp_, spv_)), p, v);                 \
        /* {Pa',Pb'} = r * KK */                                                 \
        unpk(mul2_(r2, KK), Pa, Pb);                                             \
        float K0_, K1_; unpk(KK, K0_, K1_);                                      \
        Pc = __fmaf_rn(-K1_, bp, cpv);                                           \
    } while (0)

    {
        float zcur = ZLDS(0);
        // t = 0, 1 peeled (no history store)
        {
            const float znext = ZLDS(1);
            FW_MATH(zcur);
            zcur = znext;
        }
        {
            const float znext = ZLDS(2);
            FW_MATH(zcur);
            zcur = znext;
        }
        // t in [2,126]: store always (no guard)
#pragma unroll 5
        for (int t = 2; t <= 126; t++) {
            const float znext = ZLDS(t + 1);
            FW_MATH(zcur);
            const int m_ = t - 2;
            g_F[m_ * SS + s] = make_float4(p, v, Pa, Pb);
            sD[m_ * 96 + tid] = Pc;
            zcur = znext;
        }
        // t = 127 peeled (no store)
        FW_MATH(zcur);
    }
#undef FW_MATH

    // loss at t = 127 (smoothed == filtered)
    float acc;
    {
        const float zf = ZLDS(TT - 1);
        float e = zf - p;
        e = (e >  FOLD_c) ? e - TWO_PI : e;
        e = (e < -FOLD_c) ? e + TWO_PI : e;
        const float Sv = Pa + r;
        sSv[(ch * NSLOT + 125) * 32 + lane] = Sv;
        acc = Sv * e * e;
    }

    // =========================== BACKWARD RTS (packed f32x2) ===========================
    float c0 = p, c1 = v;
    u2    cQ = pk(Pa, Pb);   // {Q00, Q01} carried packed
    float Q11 = Pc;

    float4 Fa[4], Fb[4];
    float  Ca[4], Cb[4], Za[4], Zb[4];

#define BW_LOADC(F_, C_, Z_, tq)                                                 \
    do {                                                                         \
        const int _m = max((tq) - 2, 0);                                         \
        F_ = g_F[_m * SS + s];                                                   \
        C_ = sD[_m * 96 + tid];                                                  \
        Z_ = sZ[((_m + 2) * 3 + ch) * 33 + lane];                                \
    } while (0)

#define BW_STEP(Fv, Cv, Zv, tc)                                                  \
    do {                                                                         \
        const float fp = (Fv).x, fv = (Fv).y, fa = (Fv).z, fb = (Fv).w;          \
        const float fc = (Cv);                                                   \
        const float th   = tanh_fast(100.0f * fv);                               \
        const float spv_ = __fmaf_rn(-Df_c, th, gd * fv);                        \
        const float g_   = __fmaf_rn(Ag_c, th * th, gdmAg_c);                    \
        const float spp_ = __fmaf_rn(DT, fv, fp);                                \
        const float bdc  = __fmaf_rn(DT, fc, fb);                                \
        const float ap   = __fmaf_rn(DT, fb + bdc, fa) + qp;                     \
        const float bp   = g_ * bdc;                                             \
        const float cpv  = __fmaf_rn(g_ * g_, fc, qv);                           \
        const float idet = rcp_fast(__fmaf_rn(ap, cpv, -bp * bp));               \
        float cpvI, bpI;                                                         \
        unpk(mul2_(pk(cpv, bp), pk(idet, idet)), cpvI, bpI);                     \
        const float apI  = ap * idet;                                            \
        const u2 fbfc = pk(fb, fc);                                              \
        const u2 fafb = pk(fa, fb);                                              \
        const u2 uw   = fma2_(DT2, fbfc, fafb);            /* {u0,w0} */         \
        const u2 u1w1 = mul2_(pk(g_, g_), fbfc);           /* {u1,w1} */         \
        const u2 nbpI2 = pk(-bpI, -bpI);                                         \
        const u2 G0 = fma2_(uw,   pk(cpvI, cpvI), mul2_(u1w1, nbpI2));           \
        const u2 G1 = fma2_(u1w1, pk(apI,  apI),  mul2_(uw,   nbpI2));           \
        const float ds0 = c0 - spp_;                                             \
        const float ds1 = c1 - spv_;                                             \
        unpk(fma2_(G0, pk(ds0, ds0),                                             \
                   fma2_(G1, pk(ds1, ds1), pk(fp, fv))), c0, c1);                \
        float E00, E01;                                                          \
        unpk(add2_(cQ, NEG2(pk(ap, bp))), E00, E01);                             \
        const float E11 = Q11 - cpv;                                             \
        const u2 M0 = fma2_(G0, pk(E00, E00), mul2_(G1, pk(E01, E01)));          \
        const u2 M1 = fma2_(G0, pk(E01, E01), mul2_(G1, pk(E11, E11)));          \
        float M00, M10, M01, M11;                                                \
        unpk(M0, M00, M10); unpk(M1, M01, M11);                                  \
        cQ = fma2_(pk(M00, M00), G0, fma2_(pk(M01, M01), G1, fafb));             \
        float G00_, G10_, G01_, G11_;                                            \
        unpk(G0, G00_, G10_); unpk(G1, G01_, G11_);                              \
        Q11 = __fmaf_rn(M10, G10_, __fmaf_rn(M11, G11_, fc));                    \
        float nQ00, nQ01; unpk(cQ, nQ00, nQ01);                                  \
        const float Sv = nQ00 + r;                                               \
        float e = (Zv) - c0;                                                     \
        e = (e >  FOLD_c) ? e - TWO_PI : e;                                      \
        e = (e < -FOLD_c) ? e + TWO_PI : e;                                      \
        acc = __fmaf_rn(Sv * e, e, acc);                                         \
        sSv[(ch * NSLOT + ((tc) - 2)) * 32 + lane] = Sv;                         \
    } while (0)

    // preload: Fa[j] <- t=126-j, Fb[j] <- t=122-j
#pragma unroll
    for (int j = 0; j < 4; j++) BW_LOADC(Fa[j], Ca[j], Za[j], 126 - j);
#pragma unroll
    for (int j = 0; j < 4; j++) BW_LOADC(Fb[j], Cb[j], Zb[j], 122 - j);

    // main loop: 15 x 8 = 120 steps, t = 126 down to 7 (no guards)
    for (int ii = 0; ii < 15; ii++) {
        const int head_a = 126 - 8 * ii;
        const int pre_a  = head_a - 8;
#pragma unroll
        for (int j = 0; j < 4; j++) {
            const float4 Fv = Fa[j];
            const float  Cv = Ca[j], Zv = Za[j];
            BW_LOADC(Fa[j], Ca[j], Za[j], pre_a - j);
            BW_STEP(Fv, Cv, Zv, head_a - j);
        }
        const int head_b = head_a - 4;
        const int pre_b  = head_b - 8;
#pragma unroll
        for (int j = 0; j < 4; j++) {
            const float4 Fv = Fb[j];
            const float  Cv = Cb[j], Zv = Zb[j];
            BW_LOADC(Fb[j], Cb[j], Zb[j], pre_b - j);
            BW_STEP(Fv, Cv, Zv, head_b - j);
        }
    }
    // tail: t = 6,5,4,3 from bank A, t = 2 from bank B (no loads, no guards)
    BW_STEP(Fa[0], Ca[0], Za[0], 6);
    BW_STEP(Fa[1], Ca[1], Za[1], 5);
    BW_STEP(Fa[2], Ca[2], Za[2], 4);
    BW_STEP(Fa[3], Ca[3], Za[3], 3);
    BW_STEP(Fb[0], Cb[0], Zb[0], 2);
#undef BW_LOADC
#undef BW_STEP
#undef ZLDS

    // =========================== in-block combine ===========================
    __syncthreads();

    float total = acc;
    // 126*32 = 4032 = 42 * 96 exactly
    for (int idx = tid; idx < NSLOT * 32; idx += 96) {
        const int u = idx >> 5;
        const int l = idx & 31;
        total += sSv[(0 * NSLOT + u) * 32 + l]
               * sSv[(1 * NSLOT + u) * 32 + l]
               * sSv[(2 * NSLOT + u) * 32 + l];
    }
    // warp-level reduce, then 3 partials via smem
#pragma unroll
    for (int k = 16; k > 0; k >>= 1)
        total += __shfl_xor_sync(0xffffffffu, total, k);
    __syncthreads();            // all Sv reads done; reuse smem front as scratch
    if (lane == 0) sSv[ch] = total;
    __syncthreads();
    if (tid == 0) g_bsum[blockIdx.x] = sSv[0] + sSv[1] + sSv[2];
    __threadfence();
    if (tid == 0) {
        const unsigned int old = atomicInc(&g_cnt, 127u);
        sLast = (old == 127u);
    }
    __syncthreads();

    // last block: deterministic final reduce of 128 partials
    if (sLast && tid < 32) {
        __threadfence();
        double ds = 0.0;
#pragma unroll
        for (int j = 0; j < 4; j++) ds += (double)g_bsum[tid * 4 + j];
#pragma unroll
        for (int k = 16; k > 0; k >>= 1)
            ds += __shfl_xor_sync(0xffffffffu, ds, k);
        if (tid == 0) out[0] = (float)ds;
    }
}

// ---------------- launch ----------------
extern "C" void kernel_launch(void* const* d_in, const int* in_sizes, int n_in,
                              void* d_out, int out_size) {
    const float* params = nullptr;
    const float* covp   = nullptr;
    const float* init   = nullptr;
    const float* meas   = nullptr;

    for (int i = 0; i < n_in; i++) {
        if      (in_sizes[i] == 4)            params = (const float*)d_in[i];
        else if (in_sizes[i] == 7)            covp   = (const float*)d_in[i];
        else if (in_sizes[i] == BB * 6)       init   = (const float*)d_in[i];
        else if (in_sizes[i] == BB * TT * 3)  meas   = (const float*)d_in[i];
    }
    if (!params && n_in > 0) params = (const float*)d_in[0];
    if (!covp   && n_in > 1) covp   = (const float*)d_in[1];
    if (!init   && n_in > 2) init   = (const float*)d_in[2];
    if (!meas   && n_in > 3) meas   = (const float*)d_in[3];

    static int smem_set = 0;
    if (!smem_set) {
        cudaFuncSetAttribute(k_all, cudaFuncAttributeMaxDynamicSharedMemorySize,
                             SMEM_BYTES);
        smem_set = 1;
    }

    k_all<<<128, 96, SMEM_BYTES>>>(params, covp, init, meas, (float*)d_out);
}

// round 15
// speedup vs baseline: 1.0115x; 1.0115x over previous
#include <cuda_runtime.h>
#include <math.h>

#define BB 4096
#define TT 128
#define SS 12288              // 3 * BB channel-chains
#define NSLOT 126             // loss slots u = t-2, t in [2,127]
#define NG 125                // filtered-history slots, t in [2,126], m = t-2

// shared memory layout (floats)
#define SZ_Z   (384 * 33)             // z staged: [k=t*3+ch][lane] padded
#define SZ_SV  (3 * NSLOT * 32)       // Sv table: [ch][u][lane]
#define SZ_D   (NG * 96)              // Pc history: [m][tid]
#define SMEM_FLOATS (SZ_Z + SZ_SV + SZ_D)
#define SMEM_BYTES  (SMEM_FLOATS * 4)

// ---------------- device scratch (no allocations allowed) ----------------
__device__ float4 g_F[NG * SS];    // filtered p,v,Pa,Pb
__device__ float  g_bsum[128];     // per-block partials
__device__ unsigned int g_cnt;     // last-block gate (self-resetting)

static __device__ __forceinline__ float sigmoidf_(float x) {
    return 1.0f / (1.0f + expf(-x));
}
static __device__ __forceinline__ float tanh_fast(float x) {
    float y; asm("tanh.approx.f32 %0, %1;" : "=f"(y) : "f"(x)); return y;
}
static __device__ __forceinline__ float rcp_fast(float x) {
    float y; asm("rcp.approx.f32 %0, %1;" : "=f"(y) : "f"(x)); return y;
}

__global__ void __launch_bounds__(96, 1)
k_all(const float* __restrict__ params,
      const float* __restrict__ covp,
      const float* __restrict__ init_states,
      const float* __restrict__ zin,
      float* __restrict__ out)
{
    extern __shared__ float smem[];
    float* sZ  = smem;                   // [384][33]
    float* sSv = smem + SZ_Z;            // [3][126][32]
    float* sD  = smem + SZ_Z + SZ_SV;    // [125][96]
    __shared__ bool sLast;

    const int tid  = threadIdx.x;
    const int ch   = tid >> 5;           // warp index = channel
    const int lane = tid & 31;
    const int b    = (blockIdx.x << 5) + lane;
    const int s    = ch * BB + b;        // column in g_F

    // ---------- stage this block's measurements into smem (coalesced) ----------
    {
        const float* zblk = zin + (size_t)(blockIdx.x << 5) * (TT * 3);
#pragma unroll 4
        for (int lb = 0; lb < 32; lb++) {
            const float4 vz = reinterpret_cast<const float4*>(zblk + lb * 384)[tid];
            const int k = tid << 2;
            sZ[(k + 0) * 33 + lb] = vz.x;
            sZ[(k + 1) * 33 + lb] = vz.y;
            sZ[(k + 2) * 33 + lb] = vz.z;
            sZ[(k + 3) * 33 + lb] = vz.w;
        }
    }

    const float DT     = 1.0f / 120.0f;
    const float TWO_PI = 6.28318530717958647692f;
    const float INV2PI = 0.15915494309189533577f;
    const float FOLD   = 4.71238898038468985769f;

    const float friction = (tanhf(params[0]) + 1.0f) * 0.01f;
    const float damping  = (tanhf(params[1]) + 1.0f) * 0.01f;

    const bool  ang   = (ch == 2);
    const float r     = sigmoidf_(covp[ch]);
    const float qp    = sigmoidf_(covp[ang ? 5 : 3]);
    const float qv    = sigmoidf_(covp[ang ? 6 : 4]);
    const float gd    = 1.0f - DT * damping;
    // channel-selected constants -> one uniform branch-free code path
    const float Df_c    = ang ? 0.0f : DT * friction;
    const float Ag_c    = ang ? 0.0f : DT * friction * 100.0f;
    const float gdmAg_c = gd - Ag_c;
    const float wTP     = ang ? TWO_PI : 0.0f;        // innovation wrap gain
    const float FOLD_c  = ang ? FOLD : 3.0e38f;       // fold sentinel

    float p, v, Pa = 0.01f, Pb = 0.0f, Pc = 0.01f;
    {
        const int pi = ang ? 4 : ch;
        const int vi = ang ? 5 : (ch + 2);
        p = init_states[b * 6 + pi];
        v = init_states[b * 6 + vi];
    }

    __syncthreads();   // z staged

#define ZLDS(t) sZ[((t) * 3 + ch) * 33 + lane]

    // =========================== FORWARD EKF (branch-free step) ===========================
#define FW_MATH(zc)                                                              \
    do {                                                                         \
        const float th   = tanh_fast(100.0f * v);                                \
        const float spv_ = __fmaf_rn(-Df_c, th, gd * v);                         \
        const float g_   = __fmaf_rn(Ag_c, th * th, gdmAg_c);                    \
        const float spp_ = __fmaf_rn(DT, v, p);                                  \
        const float bdc  = __fmaf_rn(DT, Pc, Pb);                                \
        const float ap   = __fmaf_rn(DT, Pb + bdc, Pa) + qp;                     \
        const float bp   = g_ * bdc;                                             \
        const float cpv  = __fmaf_rn(g_ * g_, Pc, qv);                           \
        float innov = (zc) - spp_;                                               \
        innov = __fmaf_rn(-wTP, rintf(innov * INV2PI), innov);                   \
        const float inv = rcp_fast(ap + r);                                      \
        const float K0  = ap * inv;                                              \
        const float K1  = bp * inv;                                              \
        p  = __fmaf_rn(K0, innov, spp_);                                         \
        v  = __fmaf_rn(K1, innov, spv_);                                         \
        Pa = r * K0;                                                             \
        Pb = r * K1;                                                             \
        Pc = __fmaf_rn(-K1, bp, cpv);                                            \
    } while (0)

    {
        float zcur = ZLDS(0);
        // t = 0, 1 peeled (no history store)
        {
            const float znext = ZLDS(1);
            FW_MATH(zcur);
            zcur = znext;
        }
        {
            const float znext = ZLDS(2);
            FW_MATH(zcur);
            zcur = znext;
        }
        // t in [2,126]: store always (no guard)
#pragma unroll 5
        for (int t = 2; t <= 126; t++) {
            const float znext = ZLDS(t + 1);
            FW_MATH(zcur);
            const int m_ = t - 2;
            g_F[m_ * SS + s] = make_float4(p, v, Pa, Pb);
            sD[m_ * 96 + tid] = Pc;
            zcur = znext;
        }
        // t = 127 peeled (no store)
        FW_MATH(zcur);
    }
#undef FW_MATH

    // loss at t = 127 (smoothed == filtered)
    float acc;
    {
        const float zf = ZLDS(TT - 1);
        float e = zf - p;
        e = (e >  FOLD_c) ? e - TWO_PI : e;
        e = (e < -FOLD_c) ? e + TWO_PI : e;
        const float Sv = Pa + r;
        sSv[(ch * NSLOT + 125) * 32 + lane] = Sv;
        acc = Sv * e * e;
    }

    // =========================== BACKWARD RTS (branch-free, affine addressing) ===========================
    float c0 = p, c1 = v, Q00 = Pa, Q01 = Pb, Q11 = Pc;

    float4 Fa[4], Fb[4];
    float  Ca[4], Cb[4], Za[4], Zb[4];

    // tq is always a compile-time-reachable value >= 2: NO clamp, fully affine.
#define BW_LOADC(F_, C_, Z_, tq)                                                 \
    do {                                                                         \
        const int _m = (tq) - 2;                                                 \
        F_ = g_F[_m * SS + s];                                                   \
        C_ = sD[_m * 96 + tid];                                                  \
        Z_ = sZ[((_m + 2) * 3 + ch) * 33 + lane];                                \
    } while (0)

#define BW_STEP(Fv, Cv, Zv, tc)                                                  \
    do {                                                                         \
        const float fp = (Fv).x, fv = (Fv).y, fa = (Fv).z, fb = (Fv).w;          \
        const float fc = (Cv);                                                   \
        const float th   = tanh_fast(100.0f * fv);                               \
        const float spv_ = __fmaf_rn(-Df_c, th, gd * fv);                        \
        const float g_   = __fmaf_rn(Ag_c, th * th, gdmAg_c);                    \
        const float spp_ = __fmaf_rn(DT, fv, fp);                                \
        const float bdc  = __fmaf_rn(DT, fc, fb);                                \
        const float ap   = __fmaf_rn(DT, fb + bdc, fa) + qp;                     \
        const float bp   = g_ * bdc;                                             \
        const float cpv  = __fmaf_rn(g_ * g_, fc, qv);                           \
        const float idet = rcp_fast(__fmaf_rn(ap, cpv, -bp * bp));               \
        const float cpvI = cpv * idet;                                           \
        const float bpI  = bp  * idet;                                           \
        const float apI  = ap  * idet;                                           \
        const float u0 = __fmaf_rn(DT, fb, fa);                                  \
        const float u1 = g_ * fb;                                                \
        const float w0 = bdc;                                                    \
        const float w1 = g_ * fc;                                                \
        const float G00 = __fmaf_rn(u0, cpvI, -u1 * bpI);                        \
        const float G01 = __fmaf_rn(u1, apI,  -u0 * bpI);                        \
        const float G10 = __fmaf_rn(w0, cpvI, -w1 * bpI);                        \
        const float G11 = __fmaf_rn(w1, apI,  -w0 * bpI);                        \
        const float ds0 = c0 - spp_;                                             \
        const float ds1 = c1 - spv_;                                             \
        const float ssp = __fmaf_rn(G00, ds0, __fmaf_rn(G01, ds1, fp));          \
        const float ssv = __fmaf_rn(G10, ds0, __fmaf_rn(G11, ds1, fv));          \
        const float E00 = Q00 - ap;                                              \
        const float E01 = Q01 - bp;                                              \
        const float E11 = Q11 - cpv;                                             \
        const float M00 = __fmaf_rn(G00, E00, G01 * E01);                        \
        const float M01 = __fmaf_rn(G00, E01, G01 * E11);                        \
        const float M10 = __fmaf_rn(G10, E00, G11 * E01);                        \
        const float M11 = __fmaf_rn(G10, E01, G11 * E11);                        \
        const float nQ00 = __fmaf_rn(M00, G00, __fmaf_rn(M01, G01, fa));         \
        const float nQ01 = __fmaf_rn(M00, G10, __fmaf_rn(M01, G11, fb));         \
        const float nQ11 = __fmaf_rn(M10, G10, __fmaf_rn(M11, G11, fc));         \
        c0 = ssp; c1 = ssv; Q00 = nQ00; Q01 = nQ01; Q11 = nQ11;                  \
        const float Sv = nQ00 + r;                                               \
        float e = (Zv) - ssp;                                                    \
        e = (e >  FOLD_c) ? e - TWO_PI : e;                                      \
        e = (e < -FOLD_c) ? e + TWO_PI : e;                                      \
        acc = __fmaf_rn(Sv * e, e, acc);                                         \
        sSv[(ch * NSLOT + ((tc) - 2)) * 32 + lane] = Sv;                         \
    } while (0)

    // preload: Fa[j] <- t=126-j (126..123), Fb[j] <- t=122-j (122..119)
#pragma unroll
    for (int j = 0; j < 4; j++) BW_LOADC(Fa[j], Ca[j], Za[j], 126 - j);
#pragma unroll
    for (int j = 0; j < 4; j++) BW_LOADC(Fb[j], Cb[j], Zb[j], 122 - j);

    // main loop: 14 x 8 = 112 steps, t = 126 down to 15; all prefetch targets >= 7
    for (int ii = 0; ii < 14; ii++) {
        const int head_a = 126 - 8 * ii;
        const int pre_a  = head_a - 8;
#pragma unroll
        for (int j = 0; j < 4; j++) {
            const float4 Fv = Fa[j];
            const float  Cv = Ca[j], Zv = Za[j];
            BW_LOADC(Fa[j], Ca[j], Za[j], pre_a - j);
            BW_STEP(Fv, Cv, Zv, head_a - j);
        }
        const int head_b = head_a - 4;
        const int pre_b  = head_b - 8;
#pragma unroll
        for (int j = 0; j < 4; j++) {
            const float4 Fv = Fb[j];
            const float  Cv = Cb[j], Zv = Zb[j];
            BW_LOADC(Fb[j], Cb[j], Zb[j], pre_b - j);
            BW_STEP(Fv, Cv, Zv, head_b - j);
        }
    }
    // After main loop: Fa holds t = 14,13,12,11; Fb holds t = 10,9,8,7.
    // Tail (all indices static, all loads >= 2, no guards):
    // process 14..11 from Fa while loading Fa <- 6..3
#pragma unroll
    for (int j = 0; j < 4; j++) {
        const float4 Fv = Fa[j];
        const float  Cv = Ca[j], Zv = Za[j];
        BW_LOADC(Fa[j], Ca[j], Za[j], 6 - j);
        BW_STEP(Fv, Cv, Zv, 14 - j);
    }
    // process 10 from Fb[0] while loading Fb[0] <- 2
    {
        const float4 Fv = Fb[0];
        const float  Cv = Cb[0], Zv = Zb[0];
        BW_LOADC(Fb[0], Cb[0], Zb[0], 2);
        BW_STEP(Fv, Cv, Zv, 10);
    }
    // process 9,8,7 from Fb[1..3]
    BW_STEP(Fb[1], Cb[1], Zb[1], 9);
    BW_STEP(Fb[2], Cb[2], Zb[2], 8);
    BW_STEP(Fb[3], Cb[3], Zb[3], 7);
    // process 6..3 from Fa, then 2 from Fb[0]
    BW_STEP(Fa[0], Ca[0], Za[0], 6);
    BW_STEP(Fa[1], Ca[1], Za[1], 5);
    BW_STEP(Fa[2], Ca[2], Za[2], 4);
    BW_STEP(Fa[3], Ca[3], Za[3], 3);
    BW_STEP(Fb[0], Cb[0], Zb[0], 2);
#undef BW_LOADC
#undef BW_STEP
#undef ZLDS

    // =========================== in-block combine ===========================
    __syncthreads();

    float total = acc;
    // 126*32 = 4032 = 42 * 96 exactly
    for (int idx = tid; idx < NSLOT * 32; idx += 96) {
        const int u = idx >> 5;
        const int l = idx & 31;
        total += sSv[(0 * NSLOT + u) * 32 + l]
               * sSv[(1 * NSLOT + u) * 32 + l]
               * sSv[(2 * NSLOT + u) * 32 + l];
    }
    // warp-level reduce, then 3 partials via smem
#pragma unroll
    for (int k = 16; k > 0; k >>= 1)
        total += __shfl_xor_sync(0xffffffffu, total, k);
    __syncthreads();            // all Sv reads done; reuse smem front as scratch
    if (lane == 0) sSv[ch] = total;
    __syncthreads();
    if (tid == 0) g_bsum[blockIdx.x] = sSv[0] + sSv[1] + sSv[2];
    __threadfence();
    if (tid == 0) {
        const unsigned int old = atomicInc(&g_cnt, 127u);
        sLast = (old == 127u);
    }
    __syncthreads();

    // last block: deterministic final reduce of 128 partials
    if (sLast && tid < 32) {
        __threadfence();
        double ds = 0.0;
#pragma unroll
        for (int j = 0; j < 4; j++) ds += (double)g_bsum[tid * 4 + j];
#pragma unroll
        for (int k = 16; k > 0; k >>= 1)
            ds += __shfl_xor_sync(0xffffffffu, ds, k);
        if (tid == 0) out[0] = (float)ds;
    }
}

// ---------------- launch ----------------
extern "C" void kernel_launch(void* const* d_in, const int* in_sizes, int n_in,
                              void* d_out, int out_size) {
    const float* params = nullptr;
    const float* covp   = nullptr;
    const float* init   = nullptr;
    const float* meas   = nullptr;

    for (int i = 0; i < n_in; i++) {
        if      (in_sizes[i] == 4)            params = (const float*)d_in[i];
        else if (in_sizes[i] == 7)            covp   = (const float*)d_in[i];
        else if (in_sizes[i] == BB * 6)       init   = (const float*)d_in[i];
        else if (in_sizes[i] == BB * TT * 3)  meas   = (const float*)d_in[i];
    }
    if (!params && n_in > 0) params = (const float*)d_in[0];
    if (!covp   && n_in > 1) covp   = (const float*)d_in[1];
    if (!init   && n_in > 2) init   = (const float*)d_in[2];
    if (!meas   && n_in > 3) meas   = (const float*)d_in[3];

    static int smem_set = 0;
    if (!smem_set) {
        cudaFuncSetAttribute(k_all, cudaFuncAttributeMaxDynamicSharedMemorySize,
                             SMEM_BYTES);
        smem_set = 1;
    }

    k_all<<<128, 96, SMEM_BYTES>>>(params, covp, init, meas, (float*)d_out);
}